// round 12
// baseline (speedup 1.0000x reference)
#include <cuda_runtime.h>
#include <cuda_fp16.h>
#include <math.h>
#include <stdint.h>

#define BB 16
#define SS 2048
#define DD 512

// ---------------------------------------------------------------------------
// Scratch (device globals — no allocation allowed)
// ---------------------------------------------------------------------------
__device__ float g_Wkp[DD * DD];     // E1 @ Wk
__device__ float g_WkpT[DD * DD];    // Wkp^T
__device__ float g_Bqk[DD * DD];     // WkpT @ Wq   (B operand for q' proj)
__device__ float g_Wvp[DD * DD];     // E2 @ Wv
__device__ float g_Wvo[DD * DD];     // Wo @ Wvp
__device__ float g_bqk[DD];          // WkpT @ bq
__device__ float g_bvp[DD];          // E2 @ bv
__device__ float g_bvo[DD];          // Wo @ bvp + bo
__device__ float g_zero512[DD];      // zero-initialized

__device__ __half g_Bqk_h[DD * DD];
__device__ __half g_Wvo_h[DD * DD];
__device__ __half g_qp_h[(size_t)BB * SS * DD];    // q' = qin@Bqk^T + bqk
__device__ __half g_kin_h[(size_t)BB * SS * DD];   // fp16(k_in)
__device__ __half g_vpT_h[(size_t)BB * SS * DD];   // (v_in@Wvo^T)^T : [b][n][t]
__device__ __half g_attn_h[(size_t)BB * SS * SS];  // fp16 attn copy

// ---------------------------------------------------------------------------
// helpers
// ---------------------------------------------------------------------------
__device__ __forceinline__ uint32_t smem_u32(const void* p) {
    uint32_t a;
    asm("{ .reg .u64 t; cvta.to.shared.u64 t, %1; cvt.u32.u64 %0, t; }"
        : "=r"(a) : "l"(p));
    return a;
}
__device__ __forceinline__ void cp_async16(uint32_t dst, const void* src) {
    asm volatile("cp.async.cg.shared.global [%0], [%1], 16;"
                 :: "r"(dst), "l"(src) : "memory");
}
__device__ __forceinline__ void cp_commit() {
    asm volatile("cp.async.commit_group;" ::: "memory");
}
__device__ __forceinline__ void cp_wait1() {
    asm volatile("cp.async.wait_group 1;" ::: "memory");
}
__device__ __forceinline__ void cp_wait0() {
    asm volatile("cp.async.wait_group 0;" ::: "memory");
}
__device__ __forceinline__ void ldsm4(uint32_t r[4], uint32_t addr) {
    asm volatile("ldmatrix.sync.aligned.m8n8.x4.shared.b16 {%0,%1,%2,%3}, [%4];"
                 : "=r"(r[0]), "=r"(r[1]), "=r"(r[2]), "=r"(r[3]) : "r"(addr));
}
__device__ __forceinline__ void mma_f16(float c[4], const uint32_t a[4],
                                        uint32_t b0, uint32_t b1) {
    asm volatile(
        "mma.sync.aligned.m16n8k16.row.col.f32.f16.f16.f32 "
        "{%0,%1,%2,%3}, {%4,%5,%6,%7}, {%8,%9}, {%0,%1,%2,%3};"
        : "+f"(c[0]), "+f"(c[1]), "+f"(c[2]), "+f"(c[3])
        : "r"(a[0]), "r"(a[1]), "r"(a[2]), "r"(a[3]), "r"(b0), "r"(b1));
}

// SMEM tile: 128 rows x 128B (64 fp16). swizzle: 16B chunk ch -> ch ^ (row&7)
__device__ __forceinline__ uint32_t tile_off(int row, int ch) {
    return (uint32_t)(row * 128 + ((ch ^ (row & 7)) * 16));
}

// 64-K chunk = 4 k16 steps; per step: 4 A-ldsm + 2 B-ldsm + 16 MMA
__device__ __forceinline__ void compute_chunk_f16(
    uint32_t stA, uint32_t stB,
    const uint32_t aoff[4][4], const uint32_t boff[2][4], float c[4][4][4])
{
#pragma unroll
    for (int ks = 0; ks < 4; ks++) {
        uint32_t a[4][4], b[2][4];
#pragma unroll
        for (int i = 0; i < 4; i++) ldsm4(a[i], stA + aoff[i][ks]);
#pragma unroll
        for (int j = 0; j < 2; j++) ldsm4(b[j], stB + boff[j][ks]);
#pragma unroll
        for (int i = 0; i < 4; i++)
#pragma unroll
            for (int j = 0; j < 4; j++)
                mma_f16(c[i][j], a[i], b[j >> 1][(j & 1) * 2], b[j >> 1][(j & 1) * 2 + 1]);
    }
}

__device__ __forceinline__ void make_offsets(int lane, int m0, int n0,
                                             uint32_t aoff[4][4], uint32_t boff[2][4])
{
#pragma unroll
    for (int i = 0; i < 4; i++) {
        const int r = m0 + i * 16 + (lane & 7) + ((lane >> 3) & 1) * 8;
#pragma unroll
        for (int ks = 0; ks < 4; ks++)
            aoff[i][ks] = tile_off(r, ks * 2 + (lane >> 4));
    }
#pragma unroll
    for (int j = 0; j < 2; j++) {
        const int r = n0 + j * 16 + (lane & 7) + ((lane >> 4) & 1) * 8;
#pragma unroll
        for (int ks = 0; ks < 4; ks++)
            boff[j][ks] = tile_off(r, ks * 2 + ((lane >> 3) & 1));
    }
}

#define TG_THREADS 256
#define TG_STAGE   32768
#define TG_SMEM    (3 * TG_STAGE)

// ---------------------------------------------------------------------------
// fp16 GEMM: out = alpha * A @ B^T (+ bias). A,B fp16. 128x128 tile,
// K-chunk 64, 3-stage cp.async, 8 warps, 2 CTA/SM.
// ---------------------------------------------------------------------------
__global__ __launch_bounds__(TG_THREADS, 2)
void tgemm_f16_kernel(const __half* __restrict__ A, const __half* __restrict__ Bm,
                      float* outF, __half* outH, const float* __restrict__ bias,
                      int M, int N, int K, float alpha,
                      long long sA, long long sB, long long sC)
{
    extern __shared__ char smem[];
    const uint32_t sb = smem_u32(smem);
    const int tid  = threadIdx.x;
    const int lane = tid & 31;
    const int wid  = tid >> 5;
    const int m0   = (wid & 1) * 64;
    const int n0   = (wid >> 1) * 32;

    const long long bz = blockIdx.z;
    A  += bz * sA;
    Bm += bz * sB;
    if (outF) outF += bz * sC;
    if (outH) outH += bz * sC;

    const int rowBase = blockIdx.y * 128;
    const int colBase = blockIdx.x * 128;

    int ldRow[4], ldCh[4];
    uint32_t ldOff[4];
#pragma unroll
    for (int i = 0; i < 4; i++) {
        const int u = tid + i * 256;
        ldRow[i] = u >> 3;
        ldCh[i]  = u & 7;
        ldOff[i] = tile_off(ldRow[i], ldCh[i]);
    }

    uint32_t aoff[4][4], boff[2][4];
    make_offsets(lane, m0, n0, aoff, boff);

    float c[4][4][4];
#pragma unroll
    for (int i = 0; i < 4; i++)
#pragma unroll
        for (int j = 0; j < 4; j++)
#pragma unroll
            for (int e = 0; e < 4; e++) c[i][j][e] = 0.0f;

    const int nc = K >> 6;

    auto load_stage = [&](int cidx) {
        const uint32_t dst = sb + (uint32_t)(cidx % 3) * TG_STAGE;
        const long long kb = (long long)cidx * 64;
#pragma unroll
        for (int i = 0; i < 4; i++) {
            const long long ea = (long long)(rowBase + ldRow[i]) * K + kb + ldCh[i] * 8;
            const long long eb = (long long)(colBase + ldRow[i]) * K + kb + ldCh[i] * 8;
            cp_async16(dst +          ldOff[i], A  + ea);
            cp_async16(dst + 16384u + ldOff[i], Bm + eb);
        }
        cp_commit();
    };

    load_stage(0);
    if (nc > 1) load_stage(1);

    for (int cidx = 0; cidx < nc; cidx++) {
        if (cidx + 1 < nc) cp_wait1(); else cp_wait0();
        __syncthreads();
        if (cidx + 2 < nc) load_stage(cidx + 2);
        const uint32_t st = sb + (uint32_t)(cidx % 3) * TG_STAGE;
        compute_chunk_f16(st, st + 16384u, aoff, boff, c);
    }
    __syncthreads();

    float* sf = (float*)smem;
#pragma unroll
    for (int i = 0; i < 4; i++) {
        const int r = m0 + i * 16 + (lane >> 2);
#pragma unroll
        for (int j = 0; j < 4; j++) {
            const int cc = n0 + j * 8 + (lane & 3) * 2;
            sf[r * 136 + cc]           = c[i][j][0];
            sf[r * 136 + cc + 1]       = c[i][j][1];
            sf[(r + 8) * 136 + cc]     = c[i][j][2];
            sf[(r + 8) * 136 + cc + 1] = c[i][j][3];
        }
    }
    __syncthreads();
#pragma unroll 4
    for (int e = tid; e < 128 * 128; e += TG_THREADS) {
        const int r = e >> 7, cc = e & 127;
        float v = sf[r * 136 + cc] * alpha;
        const int gc = colBase + cc;
        if (bias) v += bias[gc];
        const long long gi = (long long)(rowBase + r) * N + gc;
        if (outF) outF[gi] = v;
        if (outH) outH[gi] = __float2half_rn(v);
    }
}

// ---------------------------------------------------------------------------
// Merged projection GEMM (z = 0: q' ; 1: vproj(trans)). A fp32 (cvt fp16
// during STS); B fp16 via cp.async. Output fp16 (+bias first).
// ---------------------------------------------------------------------------
struct ProjArgs {
    const float*  A[2];
    const __half* Bh[2];
    __half*       out[2];
    const float*  bias[2];
    int           trans[2];
};

__global__ __launch_bounds__(TG_THREADS, 2)
void tgemm_proj_kernel(ProjArgs pa, int M, int N, int K)
{
    extern __shared__ char smem[];
    const uint32_t sb = smem_u32(smem);
    const int tid  = threadIdx.x;
    const int lane = tid & 31;
    const int wid  = tid >> 5;
    const int m0   = (wid & 1) * 64;
    const int n0   = (wid >> 1) * 32;
    const int z    = blockIdx.z;

    const float* A    = pa.A[z];
    const __half* Bh  = pa.Bh[z];
    __half* out       = pa.out[z];
    const float* bias = pa.bias[z];
    const int transOut = pa.trans[z];

    const int rowBase = blockIdx.y * 128;
    const int colBase = blockIdx.x * 128;

    int ldRow[4], ldCh[4];
    uint32_t ldOff[4];
#pragma unroll
    for (int i = 0; i < 4; i++) {
        const int u = tid + i * 256;
        ldRow[i] = u >> 3;
        ldCh[i]  = u & 7;
        ldOff[i] = tile_off(ldRow[i], ldCh[i]);
    }

    uint32_t aoff[4][4], boff[2][4];
    make_offsets(lane, m0, n0, aoff, boff);

    float c[4][4][4];
#pragma unroll
    for (int i = 0; i < 4; i++)
#pragma unroll
        for (int j = 0; j < 4; j++)
#pragma unroll
            for (int e = 0; e < 4; e++) c[i][j][e] = 0.0f;

    const int nc = K >> 6;

    auto issueB = [&](int cidx) {
        const uint32_t dst = sb + 16384u + (uint32_t)(cidx % 3) * TG_STAGE;
        const long long kb = (long long)cidx * 64;
#pragma unroll
        for (int i = 0; i < 4; i++) {
            const long long eb = (long long)(colBase + ldRow[i]) * K + kb + ldCh[i] * 8;
            cp_async16(dst + ldOff[i], Bh + eb);
        }
        cp_commit();
    };
    auto ldgA = [&](int cidx, float4 ar[4][2]) {
        const long long kb = (long long)cidx * 64;
#pragma unroll
        for (int i = 0; i < 4; i++) {
            const float* p = A + (long long)(rowBase + ldRow[i]) * K + kb + ldCh[i] * 8;
            ar[i][0] = *(const float4*)(p);
            ar[i][1] = *(const float4*)(p + 4);
        }
    };
    auto stsA = [&](int cidx, const float4 ar[4][2]) {
        char* base = smem + (cidx % 3) * TG_STAGE;
#pragma unroll
        for (int i = 0; i < 4; i++) {
            uint4 t;
            __half2 h0 = __floats2half2_rn(ar[i][0].x, ar[i][0].y);
            __half2 h1 = __floats2half2_rn(ar[i][0].z, ar[i][0].w);
            __half2 h2 = __floats2half2_rn(ar[i][1].x, ar[i][1].y);
            __half2 h3 = __floats2half2_rn(ar[i][1].z, ar[i][1].w);
            t.x = *reinterpret_cast<uint32_t*>(&h0);
            t.y = *reinterpret_cast<uint32_t*>(&h1);
            t.z = *reinterpret_cast<uint32_t*>(&h2);
            t.w = *reinterpret_cast<uint32_t*>(&h3);
            *(uint4*)(base + ldOff[i]) = t;
        }
    };

    float4 ar[4][2];
    ldgA(0, ar);
    issueB(0);
    if (nc > 1) issueB(1);
    stsA(0, ar);
    if (nc > 1) ldgA(1, ar);

    for (int cidx = 0; cidx < nc; cidx++) {
        if (cidx + 1 < nc) cp_wait1(); else cp_wait0();
        __syncthreads();
        if (cidx + 2 < nc) issueB(cidx + 2);
        if (cidx + 1 < nc) stsA(cidx + 1, ar);
        if (cidx + 2 < nc) ldgA(cidx + 2, ar);
        const uint32_t st = sb + (uint32_t)(cidx % 3) * TG_STAGE;
        compute_chunk_f16(st, st + 16384u, aoff, boff, c);
    }
    __syncthreads();

    float* sf = (float*)smem;
#pragma unroll
    for (int i = 0; i < 4; i++) {
        const int r = m0 + i * 16 + (lane >> 2);
#pragma unroll
        for (int j = 0; j < 4; j++) {
            const int cc = n0 + j * 8 + (lane & 3) * 2;
            sf[r * 136 + cc]           = c[i][j][0];
            sf[r * 136 + cc + 1]       = c[i][j][1];
            sf[(r + 8) * 136 + cc]     = c[i][j][2];
            sf[(r + 8) * 136 + cc + 1] = c[i][j][3];
        }
    }
    __syncthreads();
#pragma unroll 4
    for (int e = tid; e < 128 * 128; e += TG_THREADS) {
        int r, cc;
        if (transOut) { r = e & 127; cc = e >> 7; }
        else          { r = e >> 7;  cc = e & 127; }
        float v = sf[r * 136 + cc] + bias[colBase + cc];
        long long gi;
        if (transOut) {
            const int grow = rowBase + r;
            gi = (long long)(grow >> 11) * ((long long)DD * SS)
               + (long long)(colBase + cc) * SS + (grow & 2047);
        } else {
            gi = (long long)(rowBase + r) * N + colBase + cc;
        }
        out[gi] = __float2half_rn(v);
    }
}

// ---------------------------------------------------------------------------
// fp32 SGEMM (512^3 folds): C = A @ B
// ---------------------------------------------------------------------------
__global__ __launch_bounds__(256)
void sgemm_nn_kernel(const float* __restrict__ A, const float* __restrict__ Bm,
                     float* __restrict__ C, int M, int N, int K)
{
    const int BK = 8;
    __shared__ float As[BK][128];
    __shared__ float Bs[BK][128];
    const int tid = threadIdx.x;
    const int tx = tid & 15, ty = tid >> 4;
    const int rowBase = blockIdx.y * 128, colBase = blockIdx.x * 128;
    float acc[8][8];
#pragma unroll
    for (int i = 0; i < 8; i++)
#pragma unroll
        for (int j = 0; j < 8; j++) acc[i][j] = 0.0f;

    for (int k0 = 0; k0 < K; k0 += BK) {
        {
            const int r = tid >> 1, kc = (tid & 1) * 4;
            float4 a = *reinterpret_cast<const float4*>(A + (long long)(rowBase + r) * K + k0 + kc);
            As[kc + 0][r] = a.x; As[kc + 1][r] = a.y; As[kc + 2][r] = a.z; As[kc + 3][r] = a.w;
        }
        {
            const int kr = tid >> 5, ccc = (tid & 31) * 4;
            float4 b = *reinterpret_cast<const float4*>(Bm + (long long)(k0 + kr) * N + colBase + ccc);
            Bs[kr][ccc + 0] = b.x; Bs[kr][ccc + 1] = b.y; Bs[kr][ccc + 2] = b.z; Bs[kr][ccc + 3] = b.w;
        }
        __syncthreads();
#pragma unroll
        for (int k = 0; k < BK; k++) {
            float4 a0 = *reinterpret_cast<const float4*>(&As[k][ty * 8]);
            float4 a1 = *reinterpret_cast<const float4*>(&As[k][ty * 8 + 4]);
            float4 b0 = *reinterpret_cast<const float4*>(&Bs[k][tx * 8]);
            float4 b1 = *reinterpret_cast<const float4*>(&Bs[k][tx * 8 + 4]);
            float arr[8] = {a0.x, a0.y, a0.z, a0.w, a1.x, a1.y, a1.z, a1.w};
            float brr[8] = {b0.x, b0.y, b0.z, b0.w, b1.x, b1.y, b1.z, b1.w};
#pragma unroll
            for (int i = 0; i < 8; i++)
#pragma unroll
                for (int j = 0; j < 8; j++) acc[i][j] = fmaf(arr[i], brr[j], acc[i][j]);
        }
        __syncthreads();
    }
#pragma unroll
    for (int i = 0; i < 8; i++) {
        const int r = rowBase + ty * 8 + i;
#pragma unroll
        for (int j = 0; j < 8; j += 4) {
            const int cc = colBase + tx * 8 + j;
            float4 v = {acc[i][j], acc[i][j + 1], acc[i][j + 2], acc[i][j + 3]};
            *reinterpret_cast<float4*>(C + (long long)r * N + cc) = v;
        }
    }
}

// 512x512 fp32 transpose
__global__ void transpose512_kernel(const float* __restrict__ in,
                                    float* __restrict__ out)
{
    __shared__ float t[32][33];
    const int x0 = blockIdx.x * 32, y0 = blockIdx.y * 32;
#pragma unroll
    for (int i = 0; i < 32; i += 8)
        t[threadIdx.y + i][threadIdx.x] = in[(y0 + threadIdx.y + i) * DD + x0 + threadIdx.x];
    __syncthreads();
#pragma unroll
    for (int i = 0; i < 32; i += 8)
        out[(x0 + threadIdx.y + i) * DD + y0 + threadIdx.x] = t[threadIdx.x][threadIdx.y + i];
}

// out[p] = sum_d E[p,d]*b[d] + (add ? add[p] : 0)
__global__ void fuse_bias_kernel(const float* __restrict__ E,
                                 const float* __restrict__ b,
                                 const float* __restrict__ add,
                                 float* __restrict__ out)
{
    __shared__ float red[8];
    const int p = blockIdx.x;
    float s = 0.0f;
    for (int d = threadIdx.x; d < DD; d += 256)
        s = fmaf(E[(long long)p * DD + d], b[d], s);
#pragma unroll
    for (int off = 16; off > 0; off >>= 1) s += __shfl_xor_sync(0xffffffffu, s, off);
    if ((threadIdx.x & 31) == 0) red[threadIdx.x >> 5] = s;
    __syncthreads();
    if (threadIdx.x == 0) {
        float t = 0.0f;
#pragma unroll
        for (int i = 0; i < 8; i++) t += red[i];
        out[p] = t + (add ? add[p] : 0.0f);
    }
}

// convert 2 weight matrices fp32 -> fp16
__global__ void cvt2_kernel(const float* __restrict__ s0, __half* __restrict__ d0,
                            const float* __restrict__ s1, __half* __restrict__ d1)
{
    const float* x = blockIdx.z ? s1 : s0;
    __half* y      = blockIdx.z ? d1 : d0;
    const int n = DD * DD;
    for (int i = blockIdx.x * blockDim.x + threadIdx.x; i < n;
         i += gridDim.x * blockDim.x)
        y[i] = __float2half_rn(x[i]);
}

// big fp32 -> fp16 convert (k_in)
__global__ void cvt_big_kernel(const float* __restrict__ x, __half* __restrict__ y,
                               long long n)
{
    long long i = (long long)blockIdx.x * blockDim.x + threadIdx.x;
    const long long stride = (long long)gridDim.x * blockDim.x;
    for (; i < n; i += stride) {
        float2 v = *(const float2*)(x + i * 2);
        __half2 h = __floats2half2_rn(v.x, v.y);
        *(__half2*)(y + i * 2) = h;
    }
}

// softmax rows of 2048 in place (exact fp32) + fp16 copy
__global__ __launch_bounds__(256)
void softmax2048_kernel(float* __restrict__ data, __half* __restrict__ half_out)
{
    const size_t base = (size_t)blockIdx.x * 2048;
    float* row = data + base;
    const int tid = threadIdx.x;
    __shared__ float red[8];

    float v[8];
    float m = -3.4e38f;
#pragma unroll
    for (int i = 0; i < 8; i++) { v[i] = row[tid + 256 * i]; m = fmaxf(m, v[i]); }
#pragma unroll
    for (int o = 16; o > 0; o >>= 1) m = fmaxf(m, __shfl_xor_sync(0xffffffffu, m, o));
    if ((tid & 31) == 0) red[tid >> 5] = m;
    __syncthreads();
    float bm = red[0];
#pragma unroll
    for (int i = 1; i < 8; i++) bm = fmaxf(bm, red[i]);
    __syncthreads();

    float s = 0.0f;
#pragma unroll
    for (int i = 0; i < 8; i++) { v[i] = __expf(v[i] - bm); s += v[i]; }
#pragma unroll
    for (int o = 16; o > 0; o >>= 1) s += __shfl_xor_sync(0xffffffffu, s, o);
    if ((tid & 31) == 0) red[tid >> 5] = s;
    __syncthreads();
    float bs = 0.0f;
#pragma unroll
    for (int i = 0; i < 8; i++) bs += red[i];

    const float inv = 1.0f / bs;
#pragma unroll
    for (int i = 0; i < 8; i++) {
        float r = v[i] * inv;
        const size_t idx = base + tid + 256 * i;
        data[idx] = r;
        half_out[idx] = __float2half_rn(r);
    }
}

// ---------------------------------------------------------------------------
// Launch
// ---------------------------------------------------------------------------
extern "C" void kernel_launch(void* const* d_in, const int* in_sizes, int n_in,
                              void* d_out, int out_size)
{
    const float* q_in = (const float*)d_in[0];
    const float* k_in = (const float*)d_in[1];
    const float* v_in = (const float*)d_in[2];
    const float* Wq   = (const float*)d_in[3];
    const float* bq   = (const float*)d_in[4];
    const float* Wk   = (const float*)d_in[5];
    const float* bk   = (const float*)d_in[6];   // (folded constants drop: softmax-invariant)
    const float* Wv   = (const float*)d_in[7];
    const float* bv   = (const float*)d_in[8];
    const float* E1   = (const float*)d_in[9];
    const float* E2   = (const float*)d_in[10];
    const float* Wo   = (const float*)d_in[11];
    const float* bo   = (const float*)d_in[12];
    (void)bk;

    float* outp = (float*)d_out;
    float* attn = outp + (size_t)BB * SS * DD;

    float *p_Wkp, *p_WkpT, *p_Bqk, *p_Wvp, *p_Wvo, *p_bqk, *p_bvp, *p_bvo, *p_zero;
    __half *bqk_h, *wvo_h, *p_qp, *p_kin, *p_vpT, *p_ath;
    cudaGetSymbolAddress((void**)&p_Wkp,  g_Wkp);
    cudaGetSymbolAddress((void**)&p_WkpT, g_WkpT);
    cudaGetSymbolAddress((void**)&p_Bqk,  g_Bqk);
    cudaGetSymbolAddress((void**)&p_Wvp,  g_Wvp);
    cudaGetSymbolAddress((void**)&p_Wvo,  g_Wvo);
    cudaGetSymbolAddress((void**)&p_bqk,  g_bqk);
    cudaGetSymbolAddress((void**)&p_bvp,  g_bvp);
    cudaGetSymbolAddress((void**)&p_bvo,  g_bvo);
    cudaGetSymbolAddress((void**)&p_zero, g_zero512);
    cudaGetSymbolAddress((void**)&bqk_h,  g_Bqk_h);
    cudaGetSymbolAddress((void**)&wvo_h,  g_Wvo_h);
    cudaGetSymbolAddress((void**)&p_qp,   g_qp_h);
    cudaGetSymbolAddress((void**)&p_kin,  g_kin_h);
    cudaGetSymbolAddress((void**)&p_vpT,  g_vpT_h);
    cudaGetSymbolAddress((void**)&p_ath,  g_attn_h);

    cudaFuncSetAttribute(tgemm_f16_kernel, cudaFuncAttributeMaxDynamicSharedMemorySize, TG_SMEM);
    cudaFuncSetAttribute(tgemm_proj_kernel, cudaFuncAttributeMaxDynamicSharedMemorySize, TG_SMEM);

    const int M = BB * SS;
    const float scaling = 1.0f / sqrtf((float)DD);
    const dim3 gFold(DD / 128, DD / 128, 1);

    // --- fold chain (fp32, small) ---
    cvt_big_kernel<<<2048, 256>>>(k_in, p_kin, (long long)BB * SS * DD / 2); // independent
    sgemm_nn_kernel<<<gFold, 256>>>(E1, Wk, p_Wkp, DD, DD, DD);      // Wkp = E1@Wk
    transpose512_kernel<<<dim3(16, 16), dim3(32, 8)>>>(p_Wkp, p_WkpT);
    sgemm_nn_kernel<<<gFold, 256>>>(p_WkpT, Wq, p_Bqk, DD, DD, DD);  // Bqk = Wkp^T@Wq
    sgemm_nn_kernel<<<gFold, 256>>>(E2, Wv, p_Wvp, DD, DD, DD);      // Wvp = E2@Wv
    sgemm_nn_kernel<<<gFold, 256>>>(Wo, p_Wvp, p_Wvo, DD, DD, DD);   // Wvo = Wo@Wvp
    fuse_bias_kernel<<<DD, 256>>>(p_WkpT, bq, nullptr, p_bqk);       // bqk = Wkp^T@bq
    fuse_bias_kernel<<<DD, 256>>>(E2, bv, nullptr, p_bvp);           // bvp = E2@bv
    fuse_bias_kernel<<<DD, 256>>>(Wo, p_bvp, bo, p_bvo);             // bvo = Wo@bvp + bo
    cvt2_kernel<<<dim3(128, 1, 2), 256>>>(p_Bqk, bqk_h, p_Wvo, wvo_h);

    // --- projections: q' = qin@Bqk^T + bqk ; vprojT = (v_in@Wvo^T)^T ---
    {
        ProjArgs pa;
        pa.A[0] = q_in; pa.Bh[0] = bqk_h; pa.out[0] = p_qp;  pa.bias[0] = p_bqk;  pa.trans[0] = 0;
        pa.A[1] = v_in; pa.Bh[1] = wvo_h; pa.out[1] = p_vpT; pa.bias[1] = p_zero; pa.trans[1] = 1;
        tgemm_proj_kernel<<<dim3(DD / 128, M / 128, 2), TG_THREADS, TG_SMEM>>>(pa, M, DD, DD);
    }

    // --- scores = scaling * q' @ kin^T  (row-constant bias terms dropped:
    //     softmax-invariant) -> attn region fp32 ---
    tgemm_f16_kernel<<<dim3(SS / 128, SS / 128, BB), TG_THREADS, TG_SMEM>>>(
        p_qp, p_kin, attn, nullptr, nullptr, SS, SS, DD, scaling,
        (long long)SS * DD, (long long)SS * DD, (long long)SS * SS);

    // --- softmax in place + fp16 copy ---
    softmax2048_kernel<<<BB * SS, 256>>>(attn, p_ath);

    // --- out = attn @ vprojT^T + bvo  (final GEMM eliminated by fold) ---
    tgemm_f16_kernel<<<dim3(DD / 128, SS / 128, BB), TG_THREADS, TG_SMEM>>>(
        p_ath, p_vpT, outp, nullptr, p_bvo, SS, DD, SS, 1.0f,
        (long long)SS * SS, (long long)SS * DD, (long long)SS * DD);
}

// round 13
// speedup vs baseline: 1.3256x; 1.3256x over previous
#include <cuda_runtime.h>
#include <cuda_fp16.h>
#include <math.h>
#include <stdint.h>

#define BB 16
#define SS 2048
#define DD 512

// ---------------------------------------------------------------------------
// Scratch (device globals — no allocation allowed)
// ---------------------------------------------------------------------------
__device__ float g_Wkp[DD * DD];     // E1 @ Wk
__device__ float g_Bqk[DD * DD];     // Wkp^T @ Wq   (B operand for q' proj)
__device__ float g_Wvp[DD * DD];     // E2 @ Wv
__device__ float g_Wvo[DD * DD];     // Wo @ Wvp
__device__ float g_bqk[DD];          // Wkp^T @ bq
__device__ float g_bvp[DD];          // E2 @ bv
__device__ float g_bvo[DD];          // Wo @ bvp + bo
__device__ float g_zero512[DD];      // zero-initialized

__device__ __half g_Bqk_h[DD * DD];
__device__ __half g_Wvo_h[DD * DD];
__device__ __half g_qp_h[(size_t)BB * SS * DD];    // q' = qin@Bqk^T + bqk
__device__ __half g_kin_h[(size_t)BB * SS * DD];   // fp16(k_in)
__device__ __half g_vpT_h[(size_t)BB * SS * DD];   // (v_in@Wvo^T)^T : [b][n][t]
__device__ __half g_attn_h[(size_t)BB * SS * SS];  // fp16 attn copy

// ---------------------------------------------------------------------------
// helpers
// ---------------------------------------------------------------------------
__device__ __forceinline__ uint32_t smem_u32(const void* p) {
    uint32_t a;
    asm("{ .reg .u64 t; cvta.to.shared.u64 t, %1; cvt.u32.u64 %0, t; }"
        : "=r"(a) : "l"(p));
    return a;
}
__device__ __forceinline__ void cp_async16(uint32_t dst, const void* src) {
    asm volatile("cp.async.cg.shared.global [%0], [%1], 16;"
                 :: "r"(dst), "l"(src) : "memory");
}
__device__ __forceinline__ void cp_commit() {
    asm volatile("cp.async.commit_group;" ::: "memory");
}
__device__ __forceinline__ void cp_wait1() {
    asm volatile("cp.async.wait_group 1;" ::: "memory");
}
__device__ __forceinline__ void cp_wait0() {
    asm volatile("cp.async.wait_group 0;" ::: "memory");
}
__device__ __forceinline__ void ldsm4(uint32_t r[4], uint32_t addr) {
    asm volatile("ldmatrix.sync.aligned.m8n8.x4.shared.b16 {%0,%1,%2,%3}, [%4];"
                 : "=r"(r[0]), "=r"(r[1]), "=r"(r[2]), "=r"(r[3]) : "r"(addr));
}
__device__ __forceinline__ void mma_f16(float c[4], const uint32_t a[4],
                                        uint32_t b0, uint32_t b1) {
    asm volatile(
        "mma.sync.aligned.m16n8k16.row.col.f32.f16.f16.f32 "
        "{%0,%1,%2,%3}, {%4,%5,%6,%7}, {%8,%9}, {%0,%1,%2,%3};"
        : "+f"(c[0]), "+f"(c[1]), "+f"(c[2]), "+f"(c[3])
        : "r"(a[0]), "r"(a[1]), "r"(a[2]), "r"(a[3]), "r"(b0), "r"(b1));
}

// SMEM tile: 128 rows x 128B (64 fp16). swizzle: 16B chunk ch -> ch ^ (row&7)
__device__ __forceinline__ uint32_t tile_off(int row, int ch) {
    return (uint32_t)(row * 128 + ((ch ^ (row & 7)) * 16));
}

// 64-K chunk = 4 k16 steps; per step: 4 A-ldsm + 2 B-ldsm + 16 MMA
__device__ __forceinline__ void compute_chunk_f16(
    uint32_t stA, uint32_t stB,
    const uint32_t aoff[4][4], const uint32_t boff[2][4], float c[4][4][4])
{
#pragma unroll
    for (int ks = 0; ks < 4; ks++) {
        uint32_t a[4][4], b[2][4];
#pragma unroll
        for (int i = 0; i < 4; i++) ldsm4(a[i], stA + aoff[i][ks]);
#pragma unroll
        for (int j = 0; j < 2; j++) ldsm4(b[j], stB + boff[j][ks]);
#pragma unroll
        for (int i = 0; i < 4; i++)
#pragma unroll
            for (int j = 0; j < 4; j++)
                mma_f16(c[i][j], a[i], b[j >> 1][(j & 1) * 2], b[j >> 1][(j & 1) * 2 + 1]);
    }
}

__device__ __forceinline__ void make_offsets(int lane, int m0, int n0,
                                             uint32_t aoff[4][4], uint32_t boff[2][4])
{
#pragma unroll
    for (int i = 0; i < 4; i++) {
        const int r = m0 + i * 16 + (lane & 7) + ((lane >> 3) & 1) * 8;
#pragma unroll
        for (int ks = 0; ks < 4; ks++)
            aoff[i][ks] = tile_off(r, ks * 2 + (lane >> 4));
    }
#pragma unroll
    for (int j = 0; j < 2; j++) {
        const int r = n0 + j * 16 + (lane & 7) + ((lane >> 4) & 1) * 8;
#pragma unroll
        for (int ks = 0; ks < 4; ks++)
            boff[j][ks] = tile_off(r, ks * 2 + ((lane >> 3) & 1));
    }
}

#define TG_THREADS 256
#define TG_STAGE   32768
#define TG_SMEM    (3 * TG_STAGE)

// ---------------------------------------------------------------------------
// fp16 GEMM: out = alpha * A @ B^T (+ bias). A,B fp16. 128x128 tile,
// K-chunk 64, 3-stage cp.async, 8 warps, 2 CTA/SM.
// ---------------------------------------------------------------------------
__global__ __launch_bounds__(TG_THREADS, 2)
void tgemm_f16_kernel(const __half* __restrict__ A, const __half* __restrict__ Bm,
                      float* outF, __half* outH, const float* __restrict__ bias,
                      int M, int N, int K, float alpha,
                      long long sA, long long sB, long long sC)
{
    extern __shared__ char smem[];
    const uint32_t sb = smem_u32(smem);
    const int tid  = threadIdx.x;
    const int lane = tid & 31;
    const int wid  = tid >> 5;
    const int m0   = (wid & 1) * 64;
    const int n0   = (wid >> 1) * 32;

    const long long bz = blockIdx.z;
    A  += bz * sA;
    Bm += bz * sB;
    if (outF) outF += bz * sC;
    if (outH) outH += bz * sC;

    const int rowBase = blockIdx.y * 128;
    const int colBase = blockIdx.x * 128;

    int ldRow[4], ldCh[4];
    uint32_t ldOff[4];
#pragma unroll
    for (int i = 0; i < 4; i++) {
        const int u = tid + i * 256;
        ldRow[i] = u >> 3;
        ldCh[i]  = u & 7;
        ldOff[i] = tile_off(ldRow[i], ldCh[i]);
    }

    uint32_t aoff[4][4], boff[2][4];
    make_offsets(lane, m0, n0, aoff, boff);

    float c[4][4][4];
#pragma unroll
    for (int i = 0; i < 4; i++)
#pragma unroll
        for (int j = 0; j < 4; j++)
#pragma unroll
            for (int e = 0; e < 4; e++) c[i][j][e] = 0.0f;

    const int nc = K >> 6;

    auto load_stage = [&](int cidx) {
        const uint32_t dst = sb + (uint32_t)(cidx % 3) * TG_STAGE;
        const long long kb = (long long)cidx * 64;
#pragma unroll
        for (int i = 0; i < 4; i++) {
            const long long ea = (long long)(rowBase + ldRow[i]) * K + kb + ldCh[i] * 8;
            const long long eb = (long long)(colBase + ldRow[i]) * K + kb + ldCh[i] * 8;
            cp_async16(dst +          ldOff[i], A  + ea);
            cp_async16(dst + 16384u + ldOff[i], Bm + eb);
        }
        cp_commit();
    };

    load_stage(0);
    if (nc > 1) load_stage(1);

    for (int cidx = 0; cidx < nc; cidx++) {
        if (cidx + 1 < nc) cp_wait1(); else cp_wait0();
        __syncthreads();
        if (cidx + 2 < nc) load_stage(cidx + 2);
        const uint32_t st = sb + (uint32_t)(cidx % 3) * TG_STAGE;
        compute_chunk_f16(st, st + 16384u, aoff, boff, c);
    }
    __syncthreads();

    float* sf = (float*)smem;
#pragma unroll
    for (int i = 0; i < 4; i++) {
        const int r = m0 + i * 16 + (lane >> 2);
#pragma unroll
        for (int j = 0; j < 4; j++) {
            const int cc = n0 + j * 8 + (lane & 3) * 2;
            sf[r * 136 + cc]           = c[i][j][0];
            sf[r * 136 + cc + 1]       = c[i][j][1];
            sf[(r + 8) * 136 + cc]     = c[i][j][2];
            sf[(r + 8) * 136 + cc + 1] = c[i][j][3];
        }
    }
    __syncthreads();
#pragma unroll 4
    for (int e = tid; e < 128 * 128; e += TG_THREADS) {
        const int r = e >> 7, cc = e & 127;
        float v = sf[r * 136 + cc] * alpha;
        const int gc = colBase + cc;
        if (bias) v += bias[gc];
        const long long gi = (long long)(rowBase + r) * N + gc;
        if (outF) outF[gi] = v;
        if (outH) outH[gi] = __float2half_rn(v);
    }
}

// ---------------------------------------------------------------------------
// Merged projection GEMM (z = 0: q' ; 1: vproj(trans)). A fp32 (cvt fp16
// during STS); B fp16 via cp.async. Output fp16 (+bias first).
// ---------------------------------------------------------------------------
struct ProjArgs {
    const float*  A[2];
    const __half* Bh[2];
    __half*       out[2];
    const float*  bias[2];
    int           trans[2];
};

__global__ __launch_bounds__(TG_THREADS, 2)
void tgemm_proj_kernel(ProjArgs pa, int M, int N, int K)
{
    extern __shared__ char smem[];
    const uint32_t sb = smem_u32(smem);
    const int tid  = threadIdx.x;
    const int lane = tid & 31;
    const int wid  = tid >> 5;
    const int m0   = (wid & 1) * 64;
    const int n0   = (wid >> 1) * 32;
    const int z    = blockIdx.z;

    const float* A    = pa.A[z];
    const __half* Bh  = pa.Bh[z];
    __half* out       = pa.out[z];
    const float* bias = pa.bias[z];
    const int transOut = pa.trans[z];

    const int rowBase = blockIdx.y * 128;
    const int colBase = blockIdx.x * 128;

    int ldRow[4], ldCh[4];
    uint32_t ldOff[4];
#pragma unroll
    for (int i = 0; i < 4; i++) {
        const int u = tid + i * 256;
        ldRow[i] = u >> 3;
        ldCh[i]  = u & 7;
        ldOff[i] = tile_off(ldRow[i], ldCh[i]);
    }

    uint32_t aoff[4][4], boff[2][4];
    make_offsets(lane, m0, n0, aoff, boff);

    float c[4][4][4];
#pragma unroll
    for (int i = 0; i < 4; i++)
#pragma unroll
        for (int j = 0; j < 4; j++)
#pragma unroll
            for (int e = 0; e < 4; e++) c[i][j][e] = 0.0f;

    const int nc = K >> 6;

    auto issueB = [&](int cidx) {
        const uint32_t dst = sb + 16384u + (uint32_t)(cidx % 3) * TG_STAGE;
        const long long kb = (long long)cidx * 64;
#pragma unroll
        for (int i = 0; i < 4; i++) {
            const long long eb = (long long)(colBase + ldRow[i]) * K + kb + ldCh[i] * 8;
            cp_async16(dst + ldOff[i], Bh + eb);
        }
        cp_commit();
    };
    auto ldgA = [&](int cidx, float4 ar[4][2]) {
        const long long kb = (long long)cidx * 64;
#pragma unroll
        for (int i = 0; i < 4; i++) {
            const float* p = A + (long long)(rowBase + ldRow[i]) * K + kb + ldCh[i] * 8;
            ar[i][0] = *(const float4*)(p);
            ar[i][1] = *(const float4*)(p + 4);
        }
    };
    auto stsA = [&](int cidx, const float4 ar[4][2]) {
        char* base = smem + (cidx % 3) * TG_STAGE;
#pragma unroll
        for (int i = 0; i < 4; i++) {
            uint4 t;
            __half2 h0 = __floats2half2_rn(ar[i][0].x, ar[i][0].y);
            __half2 h1 = __floats2half2_rn(ar[i][0].z, ar[i][0].w);
            __half2 h2 = __floats2half2_rn(ar[i][1].x, ar[i][1].y);
            __half2 h3 = __floats2half2_rn(ar[i][1].z, ar[i][1].w);
            t.x = *reinterpret_cast<uint32_t*>(&h0);
            t.y = *reinterpret_cast<uint32_t*>(&h1);
            t.z = *reinterpret_cast<uint32_t*>(&h2);
            t.w = *reinterpret_cast<uint32_t*>(&h3);
            *(uint4*)(base + ldOff[i]) = t;
        }
    };

    float4 ar[4][2];
    ldgA(0, ar);
    issueB(0);
    if (nc > 1) issueB(1);
    stsA(0, ar);
    if (nc > 1) ldgA(1, ar);

    for (int cidx = 0; cidx < nc; cidx++) {
        if (cidx + 1 < nc) cp_wait1(); else cp_wait0();
        __syncthreads();
        if (cidx + 2 < nc) issueB(cidx + 2);
        if (cidx + 1 < nc) stsA(cidx + 1, ar);
        if (cidx + 2 < nc) ldgA(cidx + 2, ar);
        const uint32_t st = sb + (uint32_t)(cidx % 3) * TG_STAGE;
        compute_chunk_f16(st, st + 16384u, aoff, boff, c);
    }
    __syncthreads();

    float* sf = (float*)smem;
#pragma unroll
    for (int i = 0; i < 4; i++) {
        const int r = m0 + i * 16 + (lane >> 2);
#pragma unroll
        for (int j = 0; j < 4; j++) {
            const int cc = n0 + j * 8 + (lane & 3) * 2;
            sf[r * 136 + cc]           = c[i][j][0];
            sf[r * 136 + cc + 1]       = c[i][j][1];
            sf[(r + 8) * 136 + cc]     = c[i][j][2];
            sf[(r + 8) * 136 + cc + 1] = c[i][j][3];
        }
    }
    __syncthreads();
#pragma unroll 4
    for (int e = tid; e < 128 * 128; e += TG_THREADS) {
        int r, cc;
        if (transOut) { r = e & 127; cc = e >> 7; }
        else          { r = e >> 7;  cc = e & 127; }
        float v = sf[r * 136 + cc] + bias[colBase + cc];
        long long gi;
        if (transOut) {
            const int grow = rowBase + r;
            gi = (long long)(grow >> 11) * ((long long)DD * SS)
               + (long long)(colBase + cc) * SS + (grow & 2047);
        } else {
            gi = (long long)(rowBase + r) * N + colBase + cc;
        }
        out[gi] = __float2half_rn(v);
    }
}

// ---------------------------------------------------------------------------
// Fold GEMM (512^3, fp32): 64x64 tile, BK=16, 256 thr, 4x4 microtile.
// grid (8, 8, 2) — two GEMMs per launch via z. tn: C = A^T @ B else A @ B.
// ---------------------------------------------------------------------------
struct FoldArgs {
    const float* A[2];
    const float* B[2];
    float*       C[2];
    int          tn[2];
};

__global__ __launch_bounds__(256)
void fold_gemm_kernel(FoldArgs fa)
{
    const int z = blockIdx.z;
    const float* A = fa.A[z];
    const float* B = fa.B[z];
    float* C = fa.C[z];
    const int tn = fa.tn[z];

    __shared__ float As[16][68];
    __shared__ float Bs[16][68];
    const int tid = threadIdx.x;
    const int tx = tid & 15, ty = tid >> 4;
    const int m0 = blockIdx.y * 64, n0 = blockIdx.x * 64;

    float acc[4][4];
#pragma unroll
    for (int i = 0; i < 4; i++)
#pragma unroll
        for (int j = 0; j < 4; j++) acc[i][j] = 0.0f;

    for (int k0 = 0; k0 < DD; k0 += 16) {
        if (tn) {
            // A is [K, M]; As[k][m] = A[k0+k][m0+m]
            const int kr = tid >> 4, mc = (tid & 15) * 4;
            float4 a = *(const float4*)(A + (long long)(k0 + kr) * DD + m0 + mc);
            *(float4*)&As[kr][mc] = a;
        } else {
            // A is [M, K]; As[k][m] = A[m0+m][k0+k]
            const int r = tid >> 2, kc = (tid & 3) * 4;
            float4 a = *(const float4*)(A + (long long)(m0 + r) * DD + k0 + kc);
            As[kc + 0][r] = a.x; As[kc + 1][r] = a.y;
            As[kc + 2][r] = a.z; As[kc + 3][r] = a.w;
        }
        {
            const int kr = tid >> 4, ncc = (tid & 15) * 4;
            float4 b = *(const float4*)(B + (long long)(k0 + kr) * DD + n0 + ncc);
            *(float4*)&Bs[kr][ncc] = b;
        }
        __syncthreads();
#pragma unroll
        for (int k = 0; k < 16; k++) {
            float4 a = *(const float4*)&As[k][ty * 4];
            float4 b = *(const float4*)&Bs[k][tx * 4];
            float av[4] = {a.x, a.y, a.z, a.w};
            float bv[4] = {b.x, b.y, b.z, b.w};
#pragma unroll
            for (int i = 0; i < 4; i++)
#pragma unroll
                for (int j = 0; j < 4; j++)
                    acc[i][j] = fmaf(av[i], bv[j], acc[i][j]);
        }
        __syncthreads();
    }
#pragma unroll
    for (int i = 0; i < 4; i++) {
        float4 v = {acc[i][0], acc[i][1], acc[i][2], acc[i][3]};
        *(float4*)(C + (long long)(m0 + ty * 4 + i) * DD + n0 + tx * 4) = v;
    }
}

// out[p] = sum_d E'[p,d]*b[d] + (add ? add[p] : 0); transE: E'[p,d] = E[d,p]
__global__ void fuse_bias_kernel(const float* __restrict__ E,
                                 const float* __restrict__ b,
                                 const float* __restrict__ add,
                                 float* __restrict__ out, int transE)
{
    __shared__ float red[8];
    const int p = blockIdx.x;
    float s = 0.0f;
    for (int d = threadIdx.x; d < DD; d += 256) {
        float e = transE ? E[(long long)d * DD + p] : E[(long long)p * DD + d];
        s = fmaf(e, b[d], s);
    }
#pragma unroll
    for (int off = 16; off > 0; off >>= 1) s += __shfl_xor_sync(0xffffffffu, s, off);
    if ((threadIdx.x & 31) == 0) red[threadIdx.x >> 5] = s;
    __syncthreads();
    if (threadIdx.x == 0) {
        float t = 0.0f;
#pragma unroll
        for (int i = 0; i < 8; i++) t += red[i];
        out[p] = t + (add ? add[p] : 0.0f);
    }
}

// convert 2 weight matrices fp32 -> fp16
__global__ void cvt2_kernel(const float* __restrict__ s0, __half* __restrict__ d0,
                            const float* __restrict__ s1, __half* __restrict__ d1)
{
    const float* x = blockIdx.z ? s1 : s0;
    __half* y      = blockIdx.z ? d1 : d0;
    const int n = DD * DD;
    for (int i = blockIdx.x * blockDim.x + threadIdx.x; i < n;
         i += gridDim.x * blockDim.x)
        y[i] = __float2half_rn(x[i]);
}

// big fp32 -> fp16 convert (k_in)
__global__ void cvt_big_kernel(const float* __restrict__ x, __half* __restrict__ y,
                               long long n)
{
    long long i = (long long)blockIdx.x * blockDim.x + threadIdx.x;
    const long long stride = (long long)gridDim.x * blockDim.x;
    for (; i < n; i += stride) {
        float2 v = *(const float2*)(x + i * 2);
        __half2 h = __floats2half2_rn(v.x, v.y);
        *(__half2*)(y + i * 2) = h;
    }
}

// softmax rows of 2048 in place (exact fp32) + fp16 copy
__global__ __launch_bounds__(256)
void softmax2048_kernel(float* __restrict__ data, __half* __restrict__ half_out)
{
    const size_t base = (size_t)blockIdx.x * 2048;
    float* row = data + base;
    const int tid = threadIdx.x;
    __shared__ float red[8];

    float v[8];
    float m = -3.4e38f;
#pragma unroll
    for (int i = 0; i < 8; i++) { v[i] = row[tid + 256 * i]; m = fmaxf(m, v[i]); }
#pragma unroll
    for (int o = 16; o > 0; o >>= 1) m = fmaxf(m, __shfl_xor_sync(0xffffffffu, m, o));
    if ((tid & 31) == 0) red[tid >> 5] = m;
    __syncthreads();
    float bm = red[0];
#pragma unroll
    for (int i = 1; i < 8; i++) bm = fmaxf(bm, red[i]);
    __syncthreads();

    float s = 0.0f;
#pragma unroll
    for (int i = 0; i < 8; i++) { v[i] = __expf(v[i] - bm); s += v[i]; }
#pragma unroll
    for (int o = 16; o > 0; o >>= 1) s += __shfl_xor_sync(0xffffffffu, s, o);
    if ((tid & 31) == 0) red[tid >> 5] = s;
    __syncthreads();
    float bs = 0.0f;
#pragma unroll
    for (int i = 0; i < 8; i++) bs += red[i];

    const float inv = 1.0f / bs;
#pragma unroll
    for (int i = 0; i < 8; i++) {
        float r = v[i] * inv;
        const size_t idx = base + tid + 256 * i;
        data[idx] = r;
        half_out[idx] = __float2half_rn(r);
    }
}

// ---------------------------------------------------------------------------
// Launch
// ---------------------------------------------------------------------------
extern "C" void kernel_launch(void* const* d_in, const int* in_sizes, int n_in,
                              void* d_out, int out_size)
{
    const float* q_in = (const float*)d_in[0];
    const float* k_in = (const float*)d_in[1];
    const float* v_in = (const float*)d_in[2];
    const float* Wq   = (const float*)d_in[3];
    const float* bq   = (const float*)d_in[4];
    const float* Wk   = (const float*)d_in[5];
    const float* bk   = (const float*)d_in[6];   // softmax-invariant: dropped
    const float* Wv   = (const float*)d_in[7];
    const float* bv   = (const float*)d_in[8];
    const float* E1   = (const float*)d_in[9];
    const float* E2   = (const float*)d_in[10];
    const float* Wo   = (const float*)d_in[11];
    const float* bo   = (const float*)d_in[12];
    (void)bk;

    float* outp = (float*)d_out;
    float* attn = outp + (size_t)BB * SS * DD;

    float *p_Wkp, *p_Bqk, *p_Wvp, *p_Wvo, *p_bqk, *p_bvp, *p_bvo, *p_zero;
    __half *bqk_h, *wvo_h, *p_qp, *p_kin, *p_vpT, *p_ath;
    cudaGetSymbolAddress((void**)&p_Wkp,  g_Wkp);
    cudaGetSymbolAddress((void**)&p_Bqk,  g_Bqk);
    cudaGetSymbolAddress((void**)&p_Wvp,  g_Wvp);
    cudaGetSymbolAddress((void**)&p_Wvo,  g_Wvo);
    cudaGetSymbolAddress((void**)&p_bqk,  g_bqk);
    cudaGetSymbolAddress((void**)&p_bvp,  g_bvp);
    cudaGetSymbolAddress((void**)&p_bvo,  g_bvo);
    cudaGetSymbolAddress((void**)&p_zero, g_zero512);
    cudaGetSymbolAddress((void**)&bqk_h,  g_Bqk_h);
    cudaGetSymbolAddress((void**)&wvo_h,  g_Wvo_h);
    cudaGetSymbolAddress((void**)&p_qp,   g_qp_h);
    cudaGetSymbolAddress((void**)&p_kin,  g_kin_h);
    cudaGetSymbolAddress((void**)&p_vpT,  g_vpT_h);
    cudaGetSymbolAddress((void**)&p_ath,  g_attn_h);

    cudaFuncSetAttribute(tgemm_f16_kernel, cudaFuncAttributeMaxDynamicSharedMemorySize, TG_SMEM);
    cudaFuncSetAttribute(tgemm_proj_kernel, cudaFuncAttributeMaxDynamicSharedMemorySize, TG_SMEM);

    const int M = BB * SS;
    const float scaling = 1.0f / sqrtf((float)DD);

    // --- fold chain (fp32, batched 64x64-tile fold GEMMs) ---
    cvt_big_kernel<<<2048, 256>>>(k_in, p_kin, (long long)BB * SS * DD / 2);
    {
        // level 1: Wkp = E1 @ Wk ; Wvp = E2 @ Wv
        FoldArgs f1;
        f1.A[0] = E1; f1.B[0] = Wk; f1.C[0] = p_Wkp; f1.tn[0] = 0;
        f1.A[1] = E2; f1.B[1] = Wv; f1.C[1] = p_Wvp; f1.tn[1] = 0;
        fold_gemm_kernel<<<dim3(8, 8, 2), 256>>>(f1);
    }
    {
        // level 2: Bqk = Wkp^T @ Wq ; Wvo = Wo @ Wvp
        FoldArgs f2;
        f2.A[0] = p_Wkp; f2.B[0] = Wq;    f2.C[0] = p_Bqk; f2.tn[0] = 1;
        f2.A[1] = Wo;    f2.B[1] = p_Wvp; f2.C[1] = p_Wvo; f2.tn[1] = 0;
        fold_gemm_kernel<<<dim3(8, 8, 2), 256>>>(f2);
    }
    fuse_bias_kernel<<<DD, 256>>>(p_Wkp, bq, nullptr, p_bqk, 1);  // bqk = Wkp^T@bq
    fuse_bias_kernel<<<DD, 256>>>(E2, bv, nullptr, p_bvp, 0);     // bvp = E2@bv
    fuse_bias_kernel<<<DD, 256>>>(Wo, p_bvp, bo, p_bvo, 0);       // bvo = Wo@bvp + bo
    cvt2_kernel<<<dim3(128, 1, 2), 256>>>(p_Bqk, bqk_h, p_Wvo, wvo_h);

    // --- projections: q' = qin@Bqk^T + bqk ; vprojT = (v_in@Wvo^T)^T ---
    {
        ProjArgs pa;
        pa.A[0] = q_in; pa.Bh[0] = bqk_h; pa.out[0] = p_qp;  pa.bias[0] = p_bqk;  pa.trans[0] = 0;
        pa.A[1] = v_in; pa.Bh[1] = wvo_h; pa.out[1] = p_vpT; pa.bias[1] = p_zero; pa.trans[1] = 1;
        tgemm_proj_kernel<<<dim3(DD / 128, M / 128, 2), TG_THREADS, TG_SMEM>>>(pa, M, DD, DD);
    }

    // --- scores = scaling * q' @ kin^T -> attn region fp32 ---
    tgemm_f16_kernel<<<dim3(SS / 128, SS / 128, BB), TG_THREADS, TG_SMEM>>>(
        p_qp, p_kin, attn, nullptr, nullptr, SS, SS, DD, scaling,
        (long long)SS * DD, (long long)SS * DD, (long long)SS * SS);

    // --- softmax in place + fp16 copy ---
    softmax2048_kernel<<<BB * SS, 256>>>(attn, p_ath);

    // --- out = attn @ vprojT^T + bvo ---
    tgemm_f16_kernel<<<dim3(DD / 128, SS / 128, BB), TG_THREADS, TG_SMEM>>>(
        p_ath, p_vpT, outp, nullptr, p_bvo, SS, DD, SS, 1.0f,
        (long long)SS * SS, (long long)SS * DD, (long long)SS * DD);
}

// round 14
// speedup vs baseline: 1.3423x; 1.0126x over previous
#include <cuda_runtime.h>
#include <cuda_fp16.h>
#include <math.h>
#include <stdint.h>

#define BB 16
#define SS 2048
#define DD 512

// ---------------------------------------------------------------------------
// Scratch (device globals — no allocation allowed)
// ---------------------------------------------------------------------------
__device__ float g_Wkp[DD * DD];     // E1 @ Wk
__device__ float g_Bqk[DD * DD];     // Wkp^T @ Wq
__device__ float g_Wvp[DD * DD];     // E2 @ Wv
__device__ float g_Wvo[DD * DD];     // Wo @ Wvp
__device__ float g_bqk[DD];          // Wkp^T @ bq
__device__ float g_bvp[DD];          // E2 @ bv
__device__ float g_bvo[DD];          // Wo @ bvp + bo
__device__ float g_zero512[DD];

__device__ __half g_Bqk_h[DD * DD];
__device__ __half g_Wvo_h[DD * DD];
__device__ __half g_qp_h[(size_t)BB * SS * DD];
__device__ __half g_kin_h[(size_t)BB * SS * DD];
__device__ __half g_vpT_h[(size_t)BB * SS * DD];   // [b][n][t]
__device__ __half g_attn_h[(size_t)BB * SS * SS];

// ---------------------------------------------------------------------------
// helpers
// ---------------------------------------------------------------------------
__device__ __forceinline__ uint32_t smem_u32(const void* p) {
    uint32_t a;
    asm("{ .reg .u64 t; cvta.to.shared.u64 t, %1; cvt.u32.u64 %0, t; }"
        : "=r"(a) : "l"(p));
    return a;
}
__device__ __forceinline__ void cp_async16(uint32_t dst, const void* src) {
    asm volatile("cp.async.cg.shared.global [%0], [%1], 16;"
                 :: "r"(dst), "l"(src) : "memory");
}
__device__ __forceinline__ void cp_commit() {
    asm volatile("cp.async.commit_group;" ::: "memory");
}
__device__ __forceinline__ void cp_wait1() {
    asm volatile("cp.async.wait_group 1;" ::: "memory");
}
__device__ __forceinline__ void cp_wait0() {
    asm volatile("cp.async.wait_group 0;" ::: "memory");
}
__device__ __forceinline__ void ldsm4(uint32_t r[4], uint32_t addr) {
    asm volatile("ldmatrix.sync.aligned.m8n8.x4.shared.b16 {%0,%1,%2,%3}, [%4];"
                 : "=r"(r[0]), "=r"(r[1]), "=r"(r[2]), "=r"(r[3]) : "r"(addr));
}
__device__ __forceinline__ void mma_f16(float c[4], const uint32_t a[4],
                                        uint32_t b0, uint32_t b1) {
    asm volatile(
        "mma.sync.aligned.m16n8k16.row.col.f32.f16.f16.f32 "
        "{%0,%1,%2,%3}, {%4,%5,%6,%7}, {%8,%9}, {%0,%1,%2,%3};"
        : "+f"(c[0]), "+f"(c[1]), "+f"(c[2]), "+f"(c[3])
        : "r"(a[0]), "r"(a[1]), "r"(a[2]), "r"(a[3]), "r"(b0), "r"(b1));
}

// SMEM tile: 128 rows x 128B. swizzle: 16B chunk ch -> ch ^ (row&7)
__device__ __forceinline__ uint32_t tile_off(int row, int ch) {
    return (uint32_t)(row * 128 + ((ch ^ (row & 7)) * 16));
}

// compact ldmatrix address state: base = r*128, x = r&7 ; addr = base + ((ch^x)<<4)
__device__ __forceinline__ void make_off2(int lane, int m0, int n0,
                                          uint32_t apre[4], uint32_t ax[4], int& ac0,
                                          uint32_t bpre[2], uint32_t bx[2], int& bc0)
{
#pragma unroll
    for (int i = 0; i < 4; i++) {
        const int r = m0 + i * 16 + (lane & 7) + ((lane >> 3) & 1) * 8;
        apre[i] = (uint32_t)(r * 128);
        ax[i]   = (uint32_t)(r & 7);
    }
    ac0 = lane >> 4;
#pragma unroll
    for (int j = 0; j < 2; j++) {
        const int r = n0 + j * 16 + (lane & 7) + ((lane >> 4) & 1) * 8;
        bpre[j] = (uint32_t)(r * 128);
        bx[j]   = (uint32_t)(r & 7);
    }
    bc0 = (lane >> 3) & 1;
}

// 64-K chunk = 4 k16 steps, double-buffered fragments (breaks LDSM/MMA WAR)
__device__ __forceinline__ void compute_chunk_f16(
    uint32_t stA, uint32_t stB,
    const uint32_t apre[4], const uint32_t ax[4], int ac0,
    const uint32_t bpre[2], const uint32_t bx[2], int bc0,
    float c[4][4][4])
{
    uint32_t a[2][4][4], b[2][2][4];
#pragma unroll
    for (int i = 0; i < 4; i++)
        ldsm4(a[0][i], stA + apre[i] + ((((uint32_t)ac0) ^ ax[i]) << 4));
#pragma unroll
    for (int j = 0; j < 2; j++)
        ldsm4(b[0][j], stB + bpre[j] + ((((uint32_t)bc0) ^ bx[j]) << 4));
#pragma unroll
    for (int ks = 0; ks < 4; ks++) {
        const int cur = ks & 1, nxt = cur ^ 1;
        if (ks < 3) {
            const uint32_t chA = (uint32_t)((ks + 1) * 2 + ac0);
            const uint32_t chB = (uint32_t)((ks + 1) * 2 + bc0);
#pragma unroll
            for (int i = 0; i < 4; i++)
                ldsm4(a[nxt][i], stA + apre[i] + ((chA ^ ax[i]) << 4));
#pragma unroll
            for (int j = 0; j < 2; j++)
                ldsm4(b[nxt][j], stB + bpre[j] + ((chB ^ bx[j]) << 4));
        }
#pragma unroll
        for (int i = 0; i < 4; i++)
#pragma unroll
            for (int j = 0; j < 4; j++)
                mma_f16(c[i][j], a[cur][i],
                        b[cur][j >> 1][(j & 1) * 2], b[cur][j >> 1][(j & 1) * 2 + 1]);
    }
}

#define TG_THREADS 256
#define TG_STAGE   32768
#define TG_SMEM    (3 * TG_STAGE)

// ---------------------------------------------------------------------------
// fp16 GEMM: out = alpha * A @ B^T (+ bias). 128x128 tile, K-chunk 64,
// 3-stage cp.async, 8 warps, 2 CTA/SM.
// ---------------------------------------------------------------------------
__global__ __launch_bounds__(TG_THREADS, 2)
void tgemm_f16_kernel(const __half* __restrict__ A, const __half* __restrict__ Bm,
                      float* outF, __half* outH, const float* __restrict__ bias,
                      int M, int N, int K, float alpha,
                      long long sA, long long sB, long long sC)
{
    extern __shared__ char smem[];
    const uint32_t sb = smem_u32(smem);
    const int tid  = threadIdx.x;
    const int lane = tid & 31;
    const int wid  = tid >> 5;
    const int m0   = (wid & 1) * 64;
    const int n0   = (wid >> 1) * 32;

    const long long bz = blockIdx.z;
    A  += bz * sA;
    Bm += bz * sB;
    if (outF) outF += bz * sC;
    if (outH) outH += bz * sC;

    const int rowBase = blockIdx.y * 128;
    const int colBase = blockIdx.x * 128;

    int ldRow[4], ldCh[4];
    uint32_t ldOff[4];
#pragma unroll
    for (int i = 0; i < 4; i++) {
        const int u = tid + i * 256;
        ldRow[i] = u >> 3;
        ldCh[i]  = u & 7;
        ldOff[i] = tile_off(ldRow[i], ldCh[i]);
    }

    uint32_t apre[4], ax[4], bpre[2], bx[2];
    int ac0, bc0;
    make_off2(lane, m0, n0, apre, ax, ac0, bpre, bx, bc0);

    float c[4][4][4];
#pragma unroll
    for (int i = 0; i < 4; i++)
#pragma unroll
        for (int j = 0; j < 4; j++)
#pragma unroll
            for (int e = 0; e < 4; e++) c[i][j][e] = 0.0f;

    const int nc = K >> 6;

    auto load_stage = [&](int cidx) {
        const uint32_t dst = sb + (uint32_t)(cidx % 3) * TG_STAGE;
        const long long kb = (long long)cidx * 64;
#pragma unroll
        for (int i = 0; i < 4; i++) {
            const long long ea = (long long)(rowBase + ldRow[i]) * K + kb + ldCh[i] * 8;
            const long long eb = (long long)(colBase + ldRow[i]) * K + kb + ldCh[i] * 8;
            cp_async16(dst +          ldOff[i], A  + ea);
            cp_async16(dst + 16384u + ldOff[i], Bm + eb);
        }
        cp_commit();
    };

    load_stage(0);
    if (nc > 1) load_stage(1);

    for (int cidx = 0; cidx < nc; cidx++) {
        if (cidx + 1 < nc) cp_wait1(); else cp_wait0();
        __syncthreads();
        if (cidx + 2 < nc) load_stage(cidx + 2);
        const uint32_t st = sb + (uint32_t)(cidx % 3) * TG_STAGE;
        compute_chunk_f16(st, st + 16384u, apre, ax, ac0, bpre, bx, bc0, c);
    }
    __syncthreads();

    float* sf = (float*)smem;
#pragma unroll
    for (int i = 0; i < 4; i++) {
        const int r = m0 + i * 16 + (lane >> 2);
#pragma unroll
        for (int j = 0; j < 4; j++) {
            const int cc = n0 + j * 8 + (lane & 3) * 2;
            sf[r * 136 + cc]           = c[i][j][0];
            sf[r * 136 + cc + 1]       = c[i][j][1];
            sf[(r + 8) * 136 + cc]     = c[i][j][2];
            sf[(r + 8) * 136 + cc + 1] = c[i][j][3];
        }
    }
    __syncthreads();
#pragma unroll 4
    for (int e = tid; e < 128 * 128; e += TG_THREADS) {
        const int r = e >> 7, cc = e & 127;
        float v = sf[r * 136 + cc] * alpha;
        const int gc = colBase + cc;
        if (bias) v += bias[gc];
        const long long gi = (long long)(rowBase + r) * N + gc;
        if (outF) outF[gi] = v;
        if (outH) outH[gi] = __float2half_rn(v);
    }
}

// ---------------------------------------------------------------------------
// Merged projection GEMM (z = 0: q' ; 1: vproj(trans)). A fp32 (cvt fp16
// during STS); B fp16 via cp.async. Output fp16 (+bias first).
// ---------------------------------------------------------------------------
struct ProjArgs {
    const float*  A[2];
    const __half* Bh[2];
    __half*       out[2];
    const float*  bias[2];
    int           trans[2];
};

__global__ __launch_bounds__(TG_THREADS, 2)
void tgemm_proj_kernel(ProjArgs pa, int M, int N, int K)
{
    extern __shared__ char smem[];
    const uint32_t sb = smem_u32(smem);
    const int tid  = threadIdx.x;
    const int lane = tid & 31;
    const int wid  = tid >> 5;
    const int m0   = (wid & 1) * 64;
    const int n0   = (wid >> 1) * 32;
    const int z    = blockIdx.z;

    const float* A    = pa.A[z];
    const __half* Bh  = pa.Bh[z];
    __half* out       = pa.out[z];
    const float* bias = pa.bias[z];
    const int transOut = pa.trans[z];

    const int rowBase = blockIdx.y * 128;
    const int colBase = blockIdx.x * 128;

    int ldRow[4], ldCh[4];
    uint32_t ldOff[4];
#pragma unroll
    for (int i = 0; i < 4; i++) {
        const int u = tid + i * 256;
        ldRow[i] = u >> 3;
        ldCh[i]  = u & 7;
        ldOff[i] = tile_off(ldRow[i], ldCh[i]);
    }

    uint32_t apre[4], ax[4], bpre[2], bx[2];
    int ac0, bc0;
    make_off2(lane, m0, n0, apre, ax, ac0, bpre, bx, bc0);

    float c[4][4][4];
#pragma unroll
    for (int i = 0; i < 4; i++)
#pragma unroll
        for (int j = 0; j < 4; j++)
#pragma unroll
            for (int e = 0; e < 4; e++) c[i][j][e] = 0.0f;

    const int nc = K >> 6;

    auto issueB = [&](int cidx) {
        const uint32_t dst = sb + 16384u + (uint32_t)(cidx % 3) * TG_STAGE;
        const long long kb = (long long)cidx * 64;
#pragma unroll
        for (int i = 0; i < 4; i++) {
            const long long eb = (long long)(colBase + ldRow[i]) * K + kb + ldCh[i] * 8;
            cp_async16(dst + ldOff[i], Bh + eb);
        }
        cp_commit();
    };
    auto ldgA = [&](int cidx, float4 ar[4][2]) {
        const long long kb = (long long)cidx * 64;
#pragma unroll
        for (int i = 0; i < 4; i++) {
            const float* p = A + (long long)(rowBase + ldRow[i]) * K + kb + ldCh[i] * 8;
            ar[i][0] = *(const float4*)(p);
            ar[i][1] = *(const float4*)(p + 4);
        }
    };
    auto stsA = [&](int cidx, const float4 ar[4][2]) {
        char* base = smem + (cidx % 3) * TG_STAGE;
#pragma unroll
        for (int i = 0; i < 4; i++) {
            uint4 t;
            __half2 h0 = __floats2half2_rn(ar[i][0].x, ar[i][0].y);
            __half2 h1 = __floats2half2_rn(ar[i][0].z, ar[i][0].w);
            __half2 h2 = __floats2half2_rn(ar[i][1].x, ar[i][1].y);
            __half2 h3 = __floats2half2_rn(ar[i][1].z, ar[i][1].w);
            t.x = *reinterpret_cast<uint32_t*>(&h0);
            t.y = *reinterpret_cast<uint32_t*>(&h1);
            t.z = *reinterpret_cast<uint32_t*>(&h2);
            t.w = *reinterpret_cast<uint32_t*>(&h3);
            *(uint4*)(base + ldOff[i]) = t;
        }
    };

    float4 ar[4][2];
    ldgA(0, ar);
    issueB(0);
    if (nc > 1) issueB(1);
    stsA(0, ar);
    if (nc > 1) ldgA(1, ar);

    for (int cidx = 0; cidx < nc; cidx++) {
        if (cidx + 1 < nc) cp_wait1(); else cp_wait0();
        __syncthreads();
        if (cidx + 2 < nc) issueB(cidx + 2);
        if (cidx + 1 < nc) stsA(cidx + 1, ar);
        if (cidx + 2 < nc) ldgA(cidx + 2, ar);
        const uint32_t st = sb + (uint32_t)(cidx % 3) * TG_STAGE;
        compute_chunk_f16(st, st + 16384u, apre, ax, ac0, bpre, bx, bc0, c);
    }
    __syncthreads();

    float* sf = (float*)smem;
#pragma unroll
    for (int i = 0; i < 4; i++) {
        const int r = m0 + i * 16 + (lane >> 2);
#pragma unroll
        for (int j = 0; j < 4; j++) {
            const int cc = n0 + j * 8 + (lane & 3) * 2;
            sf[r * 136 + cc]           = c[i][j][0];
            sf[r * 136 + cc + 1]       = c[i][j][1];
            sf[(r + 8) * 136 + cc]     = c[i][j][2];
            sf[(r + 8) * 136 + cc + 1] = c[i][j][3];
        }
    }
    __syncthreads();
#pragma unroll 4
    for (int e = tid; e < 128 * 128; e += TG_THREADS) {
        int r, cc;
        if (transOut) { r = e & 127; cc = e >> 7; }
        else          { r = e >> 7;  cc = e & 127; }
        float v = sf[r * 136 + cc] + bias[colBase + cc];
        long long gi;
        if (transOut) {
            const int grow = rowBase + r;
            gi = (long long)(grow >> 11) * ((long long)DD * SS)
               + (long long)(colBase + cc) * SS + (grow & 2047);
        } else {
            gi = (long long)(rowBase + r) * N + colBase + cc;
        }
        out[gi] = __float2half_rn(v);
    }
}

// ---------------------------------------------------------------------------
// Fold GEMM (512^3, fp32): 64x64 tile, BK=16, 256 thr, 4x4 microtile.
// grid (8, 8, 2). tn: C = A^T @ B else A @ B.
// ---------------------------------------------------------------------------
struct FoldArgs {
    const float* A[2];
    const float* B[2];
    float*       C[2];
    int          tn[2];
};

__global__ __launch_bounds__(256)
void fold_gemm_kernel(FoldArgs fa)
{
    const int z = blockIdx.z;
    const float* A = fa.A[z];
    const float* B = fa.B[z];
    float* C = fa.C[z];
    const int tn = fa.tn[z];

    __shared__ float As[16][68];
    __shared__ float Bs[16][68];
    const int tid = threadIdx.x;
    const int tx = tid & 15, ty = tid >> 4;
    const int m0 = blockIdx.y * 64, n0 = blockIdx.x * 64;

    float acc[4][4];
#pragma unroll
    for (int i = 0; i < 4; i++)
#pragma unroll
        for (int j = 0; j < 4; j++) acc[i][j] = 0.0f;

    for (int k0 = 0; k0 < DD; k0 += 16) {
        if (tn) {
            const int kr = tid >> 4, mc = (tid & 15) * 4;
            float4 a = *(const float4*)(A + (long long)(k0 + kr) * DD + m0 + mc);
            *(float4*)&As[kr][mc] = a;
        } else {
            const int r = tid >> 2, kc = (tid & 3) * 4;
            float4 a = *(const float4*)(A + (long long)(m0 + r) * DD + k0 + kc);
            As[kc + 0][r] = a.x; As[kc + 1][r] = a.y;
            As[kc + 2][r] = a.z; As[kc + 3][r] = a.w;
        }
        {
            const int kr = tid >> 4, ncc = (tid & 15) * 4;
            float4 b = *(const float4*)(B + (long long)(k0 + kr) * DD + n0 + ncc);
            *(float4*)&Bs[kr][ncc] = b;
        }
        __syncthreads();
#pragma unroll
        for (int k = 0; k < 16; k++) {
            float4 a = *(const float4*)&As[k][ty * 4];
            float4 b = *(const float4*)&Bs[k][tx * 4];
            float av[4] = {a.x, a.y, a.z, a.w};
            float bv[4] = {b.x, b.y, b.z, b.w};
#pragma unroll
            for (int i = 0; i < 4; i++)
#pragma unroll
                for (int j = 0; j < 4; j++)
                    acc[i][j] = fmaf(av[i], bv[j], acc[i][j]);
        }
        __syncthreads();
    }
#pragma unroll
    for (int i = 0; i < 4; i++) {
        float4 v = {acc[i][0], acc[i][1], acc[i][2], acc[i][3]};
        *(float4*)(C + (long long)(m0 + ty * 4 + i) * DD + n0 + tx * 4) = v;
    }
}

// out[p] = sum_d E'[p,d]*b[d] + (add ? add[p] : 0); transE: E'[p,d] = E[d,p]
__global__ void fuse_bias_kernel(const float* __restrict__ E,
                                 const float* __restrict__ b,
                                 const float* __restrict__ add,
                                 float* __restrict__ out, int transE)
{
    __shared__ float red[8];
    const int p = blockIdx.x;
    float s = 0.0f;
    for (int d = threadIdx.x; d < DD; d += 256) {
        float e = transE ? E[(long long)d * DD + p] : E[(long long)p * DD + d];
        s = fmaf(e, b[d], s);
    }
#pragma unroll
    for (int off = 16; off > 0; off >>= 1) s += __shfl_xor_sync(0xffffffffu, s, off);
    if ((threadIdx.x & 31) == 0) red[threadIdx.x >> 5] = s;
    __syncthreads();
    if (threadIdx.x == 0) {
        float t = 0.0f;
#pragma unroll
        for (int i = 0; i < 8; i++) t += red[i];
        out[p] = t + (add ? add[p] : 0.0f);
    }
}

// convert 2 weight matrices fp32 -> fp16
__global__ void cvt2_kernel(const float* __restrict__ s0, __half* __restrict__ d0,
                            const float* __restrict__ s1, __half* __restrict__ d1)
{
    const float* x = blockIdx.z ? s1 : s0;
    __half* y      = blockIdx.z ? d1 : d0;
    const int n = DD * DD;
    for (int i = blockIdx.x * blockDim.x + threadIdx.x; i < n;
         i += gridDim.x * blockDim.x)
        y[i] = __float2half_rn(x[i]);
}

// big fp32 -> fp16 convert (k_in)
__global__ void cvt_big_kernel(const float* __restrict__ x, __half* __restrict__ y,
                               long long n)
{
    long long i = (long long)blockIdx.x * blockDim.x + threadIdx.x;
    const long long stride = (long long)gridDim.x * blockDim.x;
    for (; i < n; i += stride) {
        float2 v = *(const float2*)(x + i * 2);
        __half2 h = __floats2half2_rn(v.x, v.y);
        *(__half2*)(y + i * 2) = h;
    }
}

// softmax rows of 2048 in place (exact fp32) + fp16 copy — vectorized
__global__ __launch_bounds__(256)
void softmax2048_kernel(float* __restrict__ data, __half* __restrict__ half_out)
{
    const size_t base = (size_t)blockIdx.x * 2048;
    float4* row4 = (float4*)(data + base);
    __half2* h2  = (__half2*)(half_out + base);
    const int tid = threadIdx.x;
    __shared__ float red[8];

    float4 v0 = row4[tid * 2];
    float4 v1 = row4[tid * 2 + 1];
    float v[8] = {v0.x, v0.y, v0.z, v0.w, v1.x, v1.y, v1.z, v1.w};

    float m = -3.4e38f;
#pragma unroll
    for (int i = 0; i < 8; i++) m = fmaxf(m, v[i]);
#pragma unroll
    for (int o = 16; o > 0; o >>= 1) m = fmaxf(m, __shfl_xor_sync(0xffffffffu, m, o));
    if ((tid & 31) == 0) red[tid >> 5] = m;
    __syncthreads();
    float bm = red[0];
#pragma unroll
    for (int i = 1; i < 8; i++) bm = fmaxf(bm, red[i]);
    __syncthreads();

    float s = 0.0f;
#pragma unroll
    for (int i = 0; i < 8; i++) { v[i] = __expf(v[i] - bm); s += v[i]; }
#pragma unroll
    for (int o = 16; o > 0; o >>= 1) s += __shfl_xor_sync(0xffffffffu, s, o);
    if ((tid & 31) == 0) red[tid >> 5] = s;
    __syncthreads();
    float bs = 0.0f;
#pragma unroll
    for (int i = 0; i < 8; i++) bs += red[i];

    const float inv = 1.0f / bs;
#pragma unroll
    for (int i = 0; i < 8; i++) v[i] *= inv;

    row4[tid * 2]     = make_float4(v[0], v[1], v[2], v[3]);
    row4[tid * 2 + 1] = make_float4(v[4], v[5], v[6], v[7]);
#pragma unroll
    for (int i = 0; i < 4; i++)
        h2[tid * 4 + i] = __floats2half2_rn(v[2 * i], v[2 * i + 1]);
}

// ---------------------------------------------------------------------------
// Launch
// ---------------------------------------------------------------------------
extern "C" void kernel_launch(void* const* d_in, const int* in_sizes, int n_in,
                              void* d_out, int out_size)
{
    const float* q_in = (const float*)d_in[0];
    const float* k_in = (const float*)d_in[1];
    const float* v_in = (const float*)d_in[2];
    const float* Wq   = (const float*)d_in[3];
    const float* bq   = (const float*)d_in[4];
    const float* Wk   = (const float*)d_in[5];
    const float* bk   = (const float*)d_in[6];   // softmax-invariant: dropped
    const float* Wv   = (const float*)d_in[7];
    const float* bv   = (const float*)d_in[8];
    const float* E1   = (const float*)d_in[9];
    const float* E2   = (const float*)d_in[10];
    const float* Wo   = (const float*)d_in[11];
    const float* bo   = (const float*)d_in[12];
    (void)bk;

    float* outp = (float*)d_out;
    float* attn = outp + (size_t)BB * SS * DD;

    float *p_Wkp, *p_Bqk, *p_Wvp, *p_Wvo, *p_bqk, *p_bvp, *p_bvo, *p_zero;
    __half *bqk_h, *wvo_h, *p_qp, *p_kin, *p_vpT, *p_ath;
    cudaGetSymbolAddress((void**)&p_Wkp,  g_Wkp);
    cudaGetSymbolAddress((void**)&p_Bqk,  g_Bqk);
    cudaGetSymbolAddress((void**)&p_Wvp,  g_Wvp);
    cudaGetSymbolAddress((void**)&p_Wvo,  g_Wvo);
    cudaGetSymbolAddress((void**)&p_bqk,  g_bqk);
    cudaGetSymbolAddress((void**)&p_bvp,  g_bvp);
    cudaGetSymbolAddress((void**)&p_bvo,  g_bvo);
    cudaGetSymbolAddress((void**)&p_zero, g_zero512);
    cudaGetSymbolAddress((void**)&bqk_h,  g_Bqk_h);
    cudaGetSymbolAddress((void**)&wvo_h,  g_Wvo_h);
    cudaGetSymbolAddress((void**)&p_qp,   g_qp_h);
    cudaGetSymbolAddress((void**)&p_kin,  g_kin_h);
    cudaGetSymbolAddress((void**)&p_vpT,  g_vpT_h);
    cudaGetSymbolAddress((void**)&p_ath,  g_attn_h);

    cudaFuncSetAttribute(tgemm_f16_kernel, cudaFuncAttributeMaxDynamicSharedMemorySize, TG_SMEM);
    cudaFuncSetAttribute(tgemm_proj_kernel, cudaFuncAttributeMaxDynamicSharedMemorySize, TG_SMEM);

    const int M = BB * SS;
    const float scaling = 1.0f / sqrtf((float)DD);

    // --- fold chain ---
    cvt_big_kernel<<<2048, 256>>>(k_in, p_kin, (long long)BB * SS * DD / 2);
    {
        FoldArgs f1;
        f1.A[0] = E1; f1.B[0] = Wk; f1.C[0] = p_Wkp; f1.tn[0] = 0;
        f1.A[1] = E2; f1.B[1] = Wv; f1.C[1] = p_Wvp; f1.tn[1] = 0;
        fold_gemm_kernel<<<dim3(8, 8, 2), 256>>>(f1);
    }
    {
        FoldArgs f2;
        f2.A[0] = p_Wkp; f2.B[0] = Wq;    f2.C[0] = p_Bqk; f2.tn[0] = 1;
        f2.A[1] = Wo;    f2.B[1] = p_Wvp; f2.C[1] = p_Wvo; f2.tn[1] = 0;
        fold_gemm_kernel<<<dim3(8, 8, 2), 256>>>(f2);
    }
    fuse_bias_kernel<<<DD, 256>>>(p_Wkp, bq, nullptr, p_bqk, 1);
    fuse_bias_kernel<<<DD, 256>>>(E2, bv, nullptr, p_bvp, 0);
    fuse_bias_kernel<<<DD, 256>>>(Wo, p_bvp, bo, p_bvo, 0);
    cvt2_kernel<<<dim3(128, 1, 2), 256>>>(p_Bqk, bqk_h, p_Wvo, wvo_h);

    // --- projections: q' = qin@Bqk^T + bqk ; vprojT = (v_in@Wvo^T)^T ---
    {
        ProjArgs pa;
        pa.A[0] = q_in; pa.Bh[0] = bqk_h; pa.out[0] = p_qp;  pa.bias[0] = p_bqk;  pa.trans[0] = 0;
        pa.A[1] = v_in; pa.Bh[1] = wvo_h; pa.out[1] = p_vpT; pa.bias[1] = p_zero; pa.trans[1] = 1;
        tgemm_proj_kernel<<<dim3(DD / 128, M / 128, 2), TG_THREADS, TG_SMEM>>>(pa, M, DD, DD);
    }

    // --- scores = scaling * q' @ kin^T -> attn region fp32 ---
    tgemm_f16_kernel<<<dim3(SS / 128, SS / 128, BB), TG_THREADS, TG_SMEM>>>(
        p_qp, p_kin, attn, nullptr, nullptr, SS, SS, DD, scaling,
        (long long)SS * DD, (long long)SS * DD, (long long)SS * SS);

    // --- softmax in place + fp16 copy ---
    softmax2048_kernel<<<BB * SS, 256>>>(attn, p_ath);

    // --- out = attn @ vprojT^T + bvo ---
    tgemm_f16_kernel<<<dim3(DD / 128, SS / 128, BB), TG_THREADS, TG_SMEM>>>(
        p_ath, p_vpT, outp, nullptr, p_bvo, SS, DD, SS, 1.0f,
        (long long)SS * SS, (long long)SS * DD, (long long)SS * DD);
}